// round 16
// baseline (speedup 1.0000x reference)
#include <cuda_runtime.h>

// ---------------------------------------------------------------------------
// LTFGW on GB300 (sm_103a). R15.
//   KEY INSIGHT: the per-pair cost matrix E = exp(-M) is a gather from a
//   pair-independent global table g_E[n][tk] = exp(-||x_n - g_tk||^2/128).
//   k1 computes g_E directly (it has dot/xsq/gsq in-block). k2's 44KB Es
//   smem slab and per-pair exps vanish; Gibbs/objective gather E rows from
//   L2 (outside the Sinkhorn loop).
//   Freed smem stages 3 of each lane's 8 plan rows (Kq, per-thread slots,
//   conflict/sync-free) -> register demand ~140 fits the (128,3)/170 cap
//   with headroom -> NO spills (R6 spilled 168MB to DRAM because per-thread
//   local regions are cold every block wave), while keeping R6's proven
//   row-split shfl structure (10 batched shfls/iter; R14's col-split put 17
//   latency-chained shfls on the critical path -> issue 42%).
// ---------------------------------------------------------------------------

#define N_NODES 10000
#define DIM 128
#define DEG 16
#define M_LOC 17
#define T_TPL 10
#define K_TPL 10
#define TK 100
#define N_PAIRS (N_NODES * T_TPL)
#define N_OUTER 5
#define N_SINK 10

__device__ float g_E[N_NODES * TK];   // exp(-||x_n - g_tk||^2 / 128)

#define LOAD10(dst, src) do { \
    const float2* _p = (const float2*)(src); \
    float2 _q0 = _p[0], _q1 = _p[1], _q2 = _p[2], _q3 = _p[3], _q4 = _p[4]; \
    dst[0]=_q0.x; dst[1]=_q0.y; dst[2]=_q1.x; dst[3]=_q1.y; dst[4]=_q2.x; \
    dst[5]=_q2.y; dst[6]=_q3.x; dst[7]=_q3.y; dst[8]=_q4.x; dst[9]=_q4.y; } while (0)

// ---------------- Stage 1: E table (register-tiled GEMM + fused epilogue) --
#define K1_NPB 32
#define K1_HALF 50
#define TF_STRIDE 129
#define X_STRIDE 36

__global__ void __launch_bounds__(128) k1_dots(const float* __restrict__ x,
                                               const float* __restrict__ tf) {
    __shared__ alignas(16) float xst[DIM * X_STRIDE];      // 18.4 KB
    __shared__ alignas(16) float tfs[K1_HALF * TF_STRIDE]; // 25.8 KB
    __shared__ float xsqs[K1_NPB];
    const int tid = threadIdx.x;
    const int nbase = blockIdx.x * K1_NPB;

    for (int idx = tid; idx < K1_NPB * DIM; idx += 128) {
        int nl = idx >> 7, e = idx & 127;
        int n = nbase + nl;
        xst[e * X_STRIDE + nl] = (n < N_NODES) ? x[n * DIM + e] : 0.f;
    }
    __syncthreads();
    if (tid < K1_NPB) {
        float acc = 0.f;
        #pragma unroll 8
        for (int e = 0; e < DIM; e++) { float c = xst[e * X_STRIDE + tid]; acc += c * c; }
        xsqs[tid] = acc;
    }

    const int tkl = (tid < 100) ? (tid % 50) : 0;
    const int qh  = (tid < 100) ? (tid / 50) : 0;

    #pragma unroll 1
    for (int s = 0; s < 2; s++) {
        __syncthreads();
        for (int idx = tid; idx < K1_HALF * DIM; idx += 128) {
            int tkr = idx >> 7, e = idx & 127;
            tfs[tkr * TF_STRIDE + e] = tf[(s * K1_HALF + tkr) * DIM + e];
        }
        __syncthreads();

        if (tid < 100) {
            float gs = 0.f;
            #pragma unroll 8
            for (int e = 0; e < DIM; e++) { float c = tfs[tkl * TF_STRIDE + e]; gs += c * c; }

            float acc[16];
            #pragma unroll
            for (int i = 0; i < 16; i++) acc[i] = 0.f;
            const float* tfp = tfs + tkl * TF_STRIDE;
            const int nlo = qh * 16;
            #pragma unroll 4
            for (int e = 0; e < DIM; e++) {
                float tv = tfp[e];
                const float4* xp = (const float4*)(xst + e * X_STRIDE + nlo);
                float4 a0 = xp[0], a1 = xp[1], a2 = xp[2], a3 = xp[3];
                acc[0]  += tv * a0.x; acc[1]  += tv * a0.y; acc[2]  += tv * a0.z; acc[3]  += tv * a0.w;
                acc[4]  += tv * a1.x; acc[5]  += tv * a1.y; acc[6]  += tv * a1.z; acc[7]  += tv * a1.w;
                acc[8]  += tv * a2.x; acc[9]  += tv * a2.y; acc[10] += tv * a2.z; acc[11] += tv * a2.w;
                acc[12] += tv * a3.x; acc[13] += tv * a3.y; acc[14] += tv * a3.z; acc[15] += tv * a3.w;
            }
            const int tk = s * K1_HALF + tkl;
            #pragma unroll
            for (int i = 0; i < 16; i++) {
                int n = nbase + nlo + i;
                if (n < N_NODES)
                    g_E[n * TK + tk] =
                        __expf(-(xsqs[nlo + i] + gs - 2.f * acc[i]) * (1.f / 128.f));
            }
        }
    }
}

// ---------------- Stage 2: FGW solver, 2 lanes/pair, 3 rows smem-staged ----
#define BT 128                 // threads per block
#define PPB 64                 // pairs per block

__global__ void __launch_bounds__(BT, 3) k2_solver(const int* __restrict__ edge_index,
                                                   const float* __restrict__ templates,
                                                   float* __restrict__ out) {
    __shared__ float Kq[30 * BT];           // 15360 B: staged rows 5..7 per lane
    __shared__ float Cts[T_TPL * K_TPL * K_TPL];
    __shared__ float ctqs[TK];
    const int tid = threadIdx.x;
    const int r = tid & 1;                  // lane parity within pair
    const int pairlo = tid >> 1;
    const int pair = blockIdx.x * PPB + pairlo;

    for (int idx = tid; idx < T_TPL * K_TPL * K_TPL; idx += BT) Cts[idx] = templates[idx];
    __syncthreads();
    for (int idx = tid; idx < TK; idx += BT) {
        int t = idx / K_TPL, j = idx - t * K_TPL;
        float s = 0.f;
        #pragma unroll
        for (int jp = 0; jp < K_TPL; jp++) { float c = Cts[t * 100 + j * 10 + jp]; s += c * c; }
        ctqs[idx] = s * 0.1f;
    }
    __syncthreads();
    if (pair >= N_PAIRS) return;            // warp-aligned tail

    const int n = pair / T_TPL;
    const int t = pair - n * T_TPL;
    const int base = 1 + 8 * r;             // first owned row: 1 or 9

    int rows[8];                            // global node ids of owned rows
    #pragma unroll
    for (int k = 0; k < 8; k++) rows[k] = edge_index[n * DEG + (base - 1 + k)];
    const float* E0 = g_E + n * TK + t * 10;

    const float P   = 1.f / 17.f;
    const float P0c = 16.f / 17.f;
    const float Q   = 0.1f;
    const float* ct = Cts + t * 100;
    const float* cq = ctqs + t * K_TPL;

    float Kr0[10];                 // row 0 (replicated both lanes)
    float Kr[50];                  // owned rows 0..4 of this lane's 8
    float* kq = Kq + tid;          // staged rows 5..7: kq[(k3*10+j)*BT]
    #pragma unroll
    for (int j = 0; j < 10; j++) Kr0[j] = 1.f / 170.f;
    #pragma unroll
    for (int ij = 0; ij < 50; ij++) Kr[ij] = 1.f / 170.f;
    #pragma unroll
    for (int ij = 0; ij < 30; ij++) kq[ij * BT] = 1.f / 170.f;

    float v[10];

    #pragma unroll 1
    for (int outer = 0; outer < N_OUTER; outer++) {
        // ---- a_j = colsum of rows 1..16 (own partial incl staged + shfl) ----
        float a[10];
        #pragma unroll
        for (int j = 0; j < 10; j++) {
            float s = Kr[j] + Kr[10 + j] + Kr[20 + j] + Kr[30 + j] + Kr[40 + j]
                    + kq[j * BT] + kq[(10 + j) * BT] + kq[(20 + j) * BT];
            a[j] = s + __shfl_xor_sync(0xffffffffu, s, 1);
        }
        // ---- Gibbs weights (R6 structure: arrays, then scale) ----
        float w[10], w0[10];
        #pragma unroll
        for (int j = 0; j < 10; j++) {
            float b = 0.f, G0 = 0.f;
            #pragma unroll
            for (int jp = 0; jp < 10; jp++) {
                float c = ct[j * 10 + jp];     // Ct symmetric
                b  += Kr0[jp] * c;
                G0 += a[jp] * c;
            }
            float c2 = cq[j];
            w[j]  = __expf(-2.f * (P   + c2 - 2.f * b));
            w0[j] = __expf(-2.f * (P0c + c2 - 2.f * G0));
        }
        // ---- Gibbs kernel: K = T * E * w (E gathered from g_E) ----
        {
            float Et[10];
            LOAD10(Et, E0);
            #pragma unroll
            for (int j = 0; j < 10; j++) Kr0[j] *= Et[j] * w0[j];
            #pragma unroll
            for (int k = 0; k < 5; k++) {
                LOAD10(Et, g_E + rows[k] * TK + t * 10);
                #pragma unroll
                for (int j = 0; j < 10; j++) Kr[k * 10 + j] *= Et[j] * w[j];
            }
            #pragma unroll
            for (int k3 = 0; k3 < 3; k3++) {
                LOAD10(Et, g_E + rows[5 + k3] * TK + t * 10);
                #pragma unroll
                for (int j = 0; j < 10; j++) {
                    float tv = kq[(k3 * 10 + j) * BT];
                    kq[(k3 * 10 + j) * BT] = tv * Et[j] * w[j];
                }
            }
        }
        // ---- Sinkhorn (primal), v starts at 1 ----
        #pragma unroll
        for (int j = 0; j < 10; j++) v[j] = 1.f;
        #pragma unroll 1
        for (int it = 0; it < N_SINK - 1; it++) {
            float s[10];
            float kv0 = 0.f;
            #pragma unroll
            for (int j = 0; j < 10; j++) kv0 += Kr0[j] * v[j];
            float u0h = 0.5f * __fdividef(P, kv0);          // half per lane
            #pragma unroll
            for (int j = 0; j < 10; j++) s[j] = Kr0[j] * u0h;
            #pragma unroll
            for (int k = 0; k < 5; k++) {
                float kv = 0.f;
                #pragma unroll
                for (int j = 0; j < 10; j++) kv += Kr[k * 10 + j] * v[j];
                float u = __fdividef(P, kv);
                #pragma unroll
                for (int j = 0; j < 10; j++) s[j] += Kr[k * 10 + j] * u;
            }
            #pragma unroll
            for (int k3 = 0; k3 < 3; k3++) {
                float tmp[10];
                #pragma unroll
                for (int j = 0; j < 10; j++) tmp[j] = kq[(k3 * 10 + j) * BT];
                float kv = 0.f;
                #pragma unroll
                for (int j = 0; j < 10; j++) kv += tmp[j] * v[j];
                float u = __fdividef(P, kv);
                #pragma unroll
                for (int j = 0; j < 10; j++) s[j] += tmp[j] * u;
            }
            #pragma unroll
            for (int j = 0; j < 10; j++) {
                float st = s[j] + __shfl_xor_sync(0xffffffffu, s[j], 1);
                v[j] = __fdividef(Q, st);
            }
        }
        // ---- last Sinkhorn iter: keep u's, final v, fold T = K o u v^T ----
        {
            float s[10], uo[8];
            float kv0 = 0.f;
            #pragma unroll
            for (int j = 0; j < 10; j++) kv0 += Kr0[j] * v[j];
            float u0 = __fdividef(P, kv0);
            float u0h = 0.5f * u0;
            #pragma unroll
            for (int j = 0; j < 10; j++) s[j] = Kr0[j] * u0h;
            #pragma unroll
            for (int k = 0; k < 5; k++) {
                float kv = 0.f;
                #pragma unroll
                for (int j = 0; j < 10; j++) kv += Kr[k * 10 + j] * v[j];
                uo[k] = __fdividef(P, kv);
                #pragma unroll
                for (int j = 0; j < 10; j++) s[j] += Kr[k * 10 + j] * uo[k];
            }
            #pragma unroll
            for (int k3 = 0; k3 < 3; k3++) {
                float tmp[10];
                #pragma unroll
                for (int j = 0; j < 10; j++) tmp[j] = kq[(k3 * 10 + j) * BT];
                float kv = 0.f;
                #pragma unroll
                for (int j = 0; j < 10; j++) kv += tmp[j] * v[j];
                uo[5 + k3] = __fdividef(P, kv);
                #pragma unroll
                for (int j = 0; j < 10; j++) s[j] += tmp[j] * uo[5 + k3];
            }
            #pragma unroll
            for (int j = 0; j < 10; j++) {
                float st = s[j] + __shfl_xor_sync(0xffffffffu, s[j], 1);
                v[j] = __fdividef(Q, st);
            }
            #pragma unroll
            for (int j = 0; j < 10; j++) Kr0[j] *= u0 * v[j];
            #pragma unroll
            for (int k = 0; k < 5; k++) {
                #pragma unroll
                for (int j = 0; j < 10; j++) Kr[k * 10 + j] *= uo[k] * v[j];
            }
            #pragma unroll
            for (int k3 = 0; k3 < 3; k3++) {
                #pragma unroll
                for (int j = 0; j < 10; j++) {
                    float tv = kq[(k3 * 10 + j) * BT];
                    kq[(k3 * 10 + j) * BT] = tv * uo[5 + k3] * v[j];
                }
            }
        }
    }

    // ---- objective: sum T_ij (0.5 M_ij + 0.5(constC_ij - 2 G_ij)),
    //      M = -log(E) gathered from g_E ----
    float a[10];
    #pragma unroll
    for (int j = 0; j < 10; j++) {
        float s = Kr[j] + Kr[10 + j] + Kr[20 + j] + Kr[30 + j] + Kr[40 + j]
                + kq[j * BT] + kq[(10 + j) * BT] + kq[(20 + j) * BT];
        a[j] = s + __shfl_xor_sync(0xffffffffu, s, 1);
    }
    float obj = 0.f;
    float cc[10];
    {
        float Et[10];
        LOAD10(Et, E0);
        #pragma unroll
        for (int j = 0; j < 10; j++) {
            float b = 0.f, G0 = 0.f;
            #pragma unroll
            for (int jp = 0; jp < 10; jp++) {
                float c = ct[j * 10 + jp];
                b  += Kr0[jp] * c;
                G0 += a[jp] * c;
            }
            float c2 = cq[j];
            float M0 = -__logf(Et[j]);
            obj += 0.5f * Kr0[j] * (0.5f * M0 + 0.5f * (P0c + c2 - 2.f * G0));
            cc[j] = 0.5f * (P + c2 - 2.f * b);
        }
    }
    #pragma unroll
    for (int k = 0; k < 5; k++) {
        float Et[10];
        LOAD10(Et, g_E + rows[k] * TK + t * 10);
        #pragma unroll
        for (int j = 0; j < 10; j++)
            obj += Kr[k * 10 + j] * (0.5f * (-__logf(Et[j])) + cc[j]);
    }
    #pragma unroll
    for (int k3 = 0; k3 < 3; k3++) {
        float Et[10];
        LOAD10(Et, g_E + rows[5 + k3] * TK + t * 10);
        #pragma unroll
        for (int j = 0; j < 10; j++)
            obj += kq[(k3 * 10 + j) * BT] * (0.5f * (-__logf(Et[j])) + cc[j]);
    }
    obj += __shfl_xor_sync(0xffffffffu, obj, 1);
    if (r == 0) out[pair] = obj;
}

// ---------------- launch: kernel launches ONLY ----------------
extern "C" void kernel_launch(void* const* d_in, const int* in_sizes, int n_in,
                              void* d_out, int out_size) {
    const float* x    = (const float*)d_in[0];
    const int*   ei   = (const int*)d_in[1];     // row 0 = src
    const float* tmpl = (const float*)d_in[2];
    const float* tf   = (const float*)d_in[3];
    float* out = (float*)d_out;

    k1_dots<<<(N_NODES + K1_NPB - 1) / K1_NPB, 128>>>(x, tf);
    k2_solver<<<(N_PAIRS + PPB - 1) / PPB, BT>>>(ei, tmpl, out);
}

// round 17
// speedup vs baseline: 1.5896x; 1.5896x over previous
#include <cuda_runtime.h>

// ---------------------------------------------------------------------------
// LTFGW on GB300 (sm_103a). R16 = the 261us-best (R6 k2 + tiled k1) with ONE
// change: k2 launch geometry (64,5) -> 204 regs/thread cap. The row-split
// k2's ~180-reg demand spilled at (128,3)'s 170 cap (DRAM 8.8% every round);
// at 204 it fits. 10 warps/SM (was 12-with-spills). Es stride 33 (PPB=32):
// same conflict-free banking as stride 65 (both == 1 mod 32, lane offset 16).
// All restructuring attempts (fused Gibbs R13, col-split R14, smem-staged
// rows R15) regressed; this keeps the proven code path byte-identical.
// ---------------------------------------------------------------------------

#define N_NODES 10000
#define DIM 128
#define DEG 16
#define M_LOC 17
#define T_TPL 10
#define K_TPL 10
#define TK 100
#define N_PAIRS (N_NODES * T_TPL)
#define N_OUTER 5
#define N_SINK 10

__device__ float g_D[N_NODES * TK];   // dot(x[n], tf[t,k])
__device__ float g_xsq[N_NODES];
__device__ float g_gsq[TK];

// ---------------- Stage 1: dots + norms (register-tiled, measured ~23us) ---
#define K1_NPB 32
#define K1_HALF 50
#define TF_STRIDE 129
#define X_STRIDE 36

__global__ void __launch_bounds__(128) k1_dots(const float* __restrict__ x,
                                               const float* __restrict__ tf) {
    __shared__ alignas(16) float xst[DIM * X_STRIDE];      // 18.4 KB
    __shared__ alignas(16) float tfs[K1_HALF * TF_STRIDE]; // 25.8 KB
    const int tid = threadIdx.x;
    const int nbase = blockIdx.x * K1_NPB;

    for (int idx = tid; idx < K1_NPB * DIM; idx += 128) {
        int nl = idx >> 7, e = idx & 127;
        int n = nbase + nl;
        xst[e * X_STRIDE + nl] = (n < N_NODES) ? x[n * DIM + e] : 0.f;
    }

    const int tkl = (tid < 100) ? (tid % 50) : 0;
    const int qh  = (tid < 100) ? (tid / 50) : 0;

    #pragma unroll 1
    for (int s = 0; s < 2; s++) {
        __syncthreads();
        for (int idx = tid; idx < K1_HALF * DIM; idx += 128) {
            int tkr = idx >> 7, e = idx & 127;
            tfs[tkr * TF_STRIDE + e] = tf[(s * K1_HALF + tkr) * DIM + e];
        }
        __syncthreads();

        if (s == 0 && tid >= 100) {
            for (int nl = tid - 100; nl < K1_NPB; nl += 28) {
                int n = nbase + nl;
                if (n < N_NODES) {
                    float acc = 0.f;
                    #pragma unroll 8
                    for (int e = 0; e < DIM; e++) {
                        float c = xst[e * X_STRIDE + nl];
                        acc += c * c;
                    }
                    g_xsq[n] = acc;
                }
            }
        }
        if (blockIdx.x == 0 && tid < K1_HALF) {
            float acc = 0.f;
            #pragma unroll 8
            for (int e = 0; e < DIM; e++) {
                float c = tfs[tid * TF_STRIDE + e];
                acc += c * c;
            }
            g_gsq[s * K1_HALF + tid] = acc;
        }
        if (tid < 100) {
            float acc[16];
            #pragma unroll
            for (int i = 0; i < 16; i++) acc[i] = 0.f;
            const float* tfp = tfs + tkl * TF_STRIDE;
            const int nlo = qh * 16;
            #pragma unroll 4
            for (int e = 0; e < DIM; e++) {
                float tv = tfp[e];
                const float4* xp = (const float4*)(xst + e * X_STRIDE + nlo);
                float4 a0 = xp[0], a1 = xp[1], a2 = xp[2], a3 = xp[3];
                acc[0]  += tv * a0.x; acc[1]  += tv * a0.y; acc[2]  += tv * a0.z; acc[3]  += tv * a0.w;
                acc[4]  += tv * a1.x; acc[5]  += tv * a1.y; acc[6]  += tv * a1.z; acc[7]  += tv * a1.w;
                acc[8]  += tv * a2.x; acc[9]  += tv * a2.y; acc[10] += tv * a2.z; acc[11] += tv * a2.w;
                acc[12] += tv * a3.x; acc[13] += tv * a3.y; acc[14] += tv * a3.z; acc[15] += tv * a3.w;
            }
            int tk = s * K1_HALF + tkl;
            #pragma unroll
            for (int i = 0; i < 16; i++) {
                int n = nbase + nlo + i;
                if (n < N_NODES) g_D[n * TK + tk] = acc[i];
            }
        }
    }
}

// ---------------- Stage 2: FGW solver, 2 lanes/pair, (64,5) geometry -------
#define BT 64                  // threads per block
#define PPB 32                 // pairs per block
#define ES_STRIDE 33           // == 1 mod 32 -> conflict-free (lane offset 16)

__global__ void __launch_bounds__(BT, 5) k2_solver(const int* __restrict__ edge_index,
                                                   const float* __restrict__ templates,
                                                   float* __restrict__ out) {
    __shared__ float Es[M_LOC * K_TPL * ES_STRIDE];   // 22440 B
    __shared__ float Cts[T_TPL * K_TPL * K_TPL];
    __shared__ float ctqs[TK];
    __shared__ float gsqs[TK];
    const int tid = threadIdx.x;
    const int r = tid & 1;                 // lane parity within pair
    const int pairlo = tid >> 1;           // pair index within block (0..31)
    const int pair = blockIdx.x * PPB + pairlo;

    for (int idx = tid; idx < T_TPL * K_TPL * K_TPL; idx += BT) Cts[idx] = templates[idx];
    for (int idx = tid; idx < TK; idx += BT) gsqs[idx] = g_gsq[idx];
    __syncthreads();
    for (int idx = tid; idx < TK; idx += BT) {
        int t = idx / K_TPL, j = idx - t * K_TPL;
        float s = 0.f;
        #pragma unroll
        for (int jp = 0; jp < K_TPL; jp++) { float c = Cts[t * 100 + j * 10 + jp]; s += c * c; }
        ctqs[idx] = s * 0.1f;
    }
    __syncthreads();
    if (pair >= N_PAIRS) return;           // exact grid (3125*32)

    const int n = pair / T_TPL;
    const int t = pair - n * T_TPL;
    const int base = 1 + 8 * r;            // first owned row: 1 or 9

    float* ep0 = Es + pairlo;                              // row 0, index j*33
    float* epo = Es + (base * 10) * ES_STRIDE + pairlo;    // own rows, (k*10+j)*33

    // ---- E = exp(-M) fill: 8 own rows per lane; lane0 also fills row 0 ----
    {
        const float* gs = gsqs + t * K_TPL;
        #pragma unroll
        for (int k = 0; k < 8; k++) {
            int rr = edge_index[n * DEG + (base - 1 + k)];
            float xsq = g_xsq[rr];
            const float* Dp = g_D + rr * TK + t * K_TPL;
            #pragma unroll
            for (int j = 0; j < 10; j++) {
                float Mij = (xsq + gs[j] - 2.f * Dp[j]) * (1.f / 128.f);
                epo[(k * 10 + j) * ES_STRIDE] = __expf(-Mij);
            }
        }
        if (r == 0) {
            float xsq = g_xsq[n];
            const float* Dp = g_D + n * TK + t * K_TPL;
            #pragma unroll
            for (int j = 0; j < 10; j++) {
                float Mij = (xsq + gs[j] - 2.f * Dp[j]) * (1.f / 128.f);
                ep0[j * ES_STRIDE] = __expf(-Mij);
            }
        }
    }
    __syncwarp();   // partner lane reads row 0 / own rows written above

    const float P   = 1.f / 17.f;
    const float P0c = 16.f / 17.f;
    const float Q   = 0.1f;
    const float* ct = Cts + t * 100;
    const float* cq = ctqs + t * K_TPL;

    float Kr0[10];                 // row 0 of plan, replicated both lanes
    float Kr[80];                  // 8 owned rows
    #pragma unroll
    for (int j = 0; j < 10; j++) Kr0[j] = 1.f / 170.f;
    #pragma unroll
    for (int ij = 0; ij < 80; ij++) Kr[ij] = 1.f / 170.f;

    float v[10];

    #pragma unroll 1
    for (int outer = 0; outer < N_OUTER; outer++) {
        // ---- a_j = colsum of rows 1..16 (own partial + partner via shfl) ----
        float a[10];
        #pragma unroll
        for (int j = 0; j < 10; j++) {
            float s = 0.f;
            #pragma unroll
            for (int k = 0; k < 8; k++) s += Kr[k * 10 + j];
            a[j] = s + __shfl_xor_sync(0xffffffffu, s, 1);
        }
        // ---- Gibbs weights ----
        float w[10], w0[10];
        #pragma unroll
        for (int j = 0; j < 10; j++) {
            float b = 0.f, G0 = 0.f;
            #pragma unroll
            for (int jp = 0; jp < 10; jp++) {
                float c = ct[j * 10 + jp];     // Ct symmetric
                b  += Kr0[jp] * c;
                G0 += a[jp] * c;
            }
            float c2 = cq[j];
            w[j]  = __expf(-2.f * (P   + c2 - 2.f * b));
            w0[j] = __expf(-2.f * (P0c + c2 - 2.f * G0));
        }
        // ---- Gibbs kernel: K = T * E * w ----
        #pragma unroll
        for (int j = 0; j < 10; j++) Kr0[j] *= ep0[j * ES_STRIDE] * w0[j];
        #pragma unroll
        for (int k = 0; k < 8; k++) {
            #pragma unroll
            for (int j = 0; j < 10; j++)
                Kr[k * 10 + j] *= epo[(k * 10 + j) * ES_STRIDE] * w[j];
        }
        // ---- Sinkhorn (primal), v starts at 1 ----
        #pragma unroll
        for (int j = 0; j < 10; j++) v[j] = 1.f;
        #pragma unroll 1
        for (int it = 0; it < N_SINK - 1; it++) {
            float s[10];
            float kv0 = 0.f;
            #pragma unroll
            for (int j = 0; j < 10; j++) kv0 += Kr0[j] * v[j];
            float u0h = 0.5f * __fdividef(P, kv0);          // half per lane
            #pragma unroll
            for (int j = 0; j < 10; j++) s[j] = Kr0[j] * u0h;
            #pragma unroll
            for (int k = 0; k < 8; k++) {
                float kv = 0.f;
                #pragma unroll
                for (int j = 0; j < 10; j++) kv += Kr[k * 10 + j] * v[j];
                float u = __fdividef(P, kv);
                #pragma unroll
                for (int j = 0; j < 10; j++) s[j] += Kr[k * 10 + j] * u;
            }
            #pragma unroll
            for (int j = 0; j < 10; j++) {
                float st = s[j] + __shfl_xor_sync(0xffffffffu, s[j], 1);
                v[j] = __fdividef(Q, st);
            }
        }
        // ---- last Sinkhorn iter: keep u's, final v, fold T = K o u v^T ----
        {
            float s[10], uo[8];
            float kv0 = 0.f;
            #pragma unroll
            for (int j = 0; j < 10; j++) kv0 += Kr0[j] * v[j];
            float u0 = __fdividef(P, kv0);
            float u0h = 0.5f * u0;
            #pragma unroll
            for (int j = 0; j < 10; j++) s[j] = Kr0[j] * u0h;
            #pragma unroll
            for (int k = 0; k < 8; k++) {
                float kv = 0.f;
                #pragma unroll
                for (int j = 0; j < 10; j++) kv += Kr[k * 10 + j] * v[j];
                uo[k] = __fdividef(P, kv);
                #pragma unroll
                for (int j = 0; j < 10; j++) s[j] += Kr[k * 10 + j] * uo[k];
            }
            #pragma unroll
            for (int j = 0; j < 10; j++) {
                float st = s[j] + __shfl_xor_sync(0xffffffffu, s[j], 1);
                v[j] = __fdividef(Q, st);
            }
            #pragma unroll
            for (int j = 0; j < 10; j++) Kr0[j] *= u0 * v[j];
            #pragma unroll
            for (int k = 0; k < 8; k++) {
                #pragma unroll
                for (int j = 0; j < 10; j++) Kr[k * 10 + j] *= uo[k] * v[j];
            }
        }
    }

    // ---- objective ----
    float a[10];
    #pragma unroll
    for (int j = 0; j < 10; j++) {
        float s = 0.f;
        #pragma unroll
        for (int k = 0; k < 8; k++) s += Kr[k * 10 + j];
        a[j] = s + __shfl_xor_sync(0xffffffffu, s, 1);
    }
    float obj = 0.f;
    #pragma unroll
    for (int j = 0; j < 10; j++) {
        float b = 0.f, G0 = 0.f;
        #pragma unroll
        for (int jp = 0; jp < 10; jp++) {
            float c = ct[j * 10 + jp];
            b  += Kr0[jp] * c;
            G0 += a[jp] * c;
        }
        float c2 = cq[j];
        float M0 = -__logf(ep0[j * ES_STRIDE]);
        obj += 0.5f * Kr0[j] * (0.5f * M0 + 0.5f * (P0c + c2 - 2.f * G0));
        float cc = 0.5f * (P + c2 - 2.f * b);
        #pragma unroll
        for (int k = 0; k < 8; k++) {
            float Mij = -__logf(epo[(k * 10 + j) * ES_STRIDE]);
            obj += Kr[k * 10 + j] * (0.5f * Mij + cc);
        }
    }
    obj += __shfl_xor_sync(0xffffffffu, obj, 1);
    if (r == 0) out[pair] = obj;
}

// ---------------- launch: kernel launches ONLY ----------------
extern "C" void kernel_launch(void* const* d_in, const int* in_sizes, int n_in,
                              void* d_out, int out_size) {
    const float* x    = (const float*)d_in[0];
    const int*   ei   = (const int*)d_in[1];     // row 0 = src
    const float* tmpl = (const float*)d_in[2];
    const float* tf   = (const float*)d_in[3];
    float* out = (float*)d_out;

    k1_dots<<<(N_NODES + K1_NPB - 1) / K1_NPB, 128>>>(x, tf);
    k2_solver<<<(N_PAIRS + PPB - 1) / PPB, BT>>>(ei, tmpl, out);
}